// round 6
// baseline (speedup 1.0000x reference)
#include <cuda_runtime.h>
#include <cstdint>

#define N 8192
#define BLOCK 256
#define CHUNKS 8          // per-thread float4 chunks: 8 * 4 * 256 = 8192 cols
#define GRID 296          // 148 SMs * 2 CTAs/SM, persistent
#define NWORDS (N / 32)   // 256 spike-mask words

// ---------------------------------------------------------------------------
// Row helpers.
// ---------------------------------------------------------------------------
__device__ __forceinline__ void load_row(float4 (&w)[CHUNKS],
                                         const float* __restrict__ W,
                                         int row, int tid) {
    const float4* wrow = (const float4*)(W + (size_t)row * N);
#pragma unroll
    for (int k = 0; k < CHUNKS; k++)
        w[k] = __ldcs(&wrow[tid + k * BLOCK]);
}

__device__ __forceinline__ void process_row(
        float4 (&w)[CHUNKS], int row, int par,
        const float* __restrict__ s_nd, const uint32_t* __restrict__ s_mask,
        float (*s_red)[BLOCK / 32],
        float mrow, float dfrow,           // prefetched membrane[row], dfire[row]
        float* __restrict__ out, int tid) {
    // Dot with 0/1 spikes via bitmask (1 KB smem instead of 32 KB floats).
    float acc = 0.0f;
#pragma unroll
    for (int k = 0; k < CHUNKS; k++) {
        int c = tid + k * BLOCK;                    // float4 index
        uint32_t b = s_mask[c >> 3] >> ((c & 7) * 4);
        acc += (b & 1u) ? w[k].x : 0.0f;
        acc += (b & 2u) ? w[k].y : 0.0f;
        acc += (b & 4u) ? w[k].z : 0.0f;
        acc += (b & 8u) ? w[k].w : 0.0f;
    }
#pragma unroll
    for (int o = 16; o > 0; o >>= 1)
        acc += __shfl_xor_sync(0xFFFFFFFFu, acc, o);
    if ((tid & 31) == 0) s_red[par][tid >> 5] = acc;
    __syncthreads();   // the ONLY barrier per row (s_red parity-buffered)

    float wsum = 0.0f;
#pragma unroll
    for (int i = 0; i < BLOCK / 32; i++) wsum += s_red[par][i];

    // LIF + row scalar, computed redundantly by every thread.
    float mem   = mrow * 0.99f + wsum;
    float spike = (mem > 1.0f) ? 1.0f : 0.0f;
    float nmem  = (spike > 0.0f) ? (mem - 0.8f) : mem;
    float ndf   = (spike > 0.0f) ? 0.0f : (dfrow + 1.0f);
    if (tid == 0) {
        out[row]         = spike;   // out_spikes
        out[N + row]     = nmem;    // new_membrane
        out[3 * N + row] = ndf;     // new_delta_fire
    }

    // Weight update: change = sign(d) * 0.005 * exp(-|d|/20), d = ndf - ndp_j.
    // d is an exact small-integer difference in fp32 -> sign/equality exact.
    float4* orow = (float4*)(out + 4 * N + (size_t)row * N);
#pragma unroll
    for (int k = 0; k < CHUNKS; k++) {
        int c = tid + k * BLOCK;
        float4 nd = ((const float4*)s_nd)[c];
        float4 o = w[k];
        {
            float d = ndf - nd.x;
            float m = 0.005f * __expf(-fabsf(d) * 0.05f);
            o.x += (d > 0.0f) ? m : ((d < 0.0f) ? -m : 0.0f);
        }
        {
            float d = ndf - nd.y;
            float m = 0.005f * __expf(-fabsf(d) * 0.05f);
            o.y += (d > 0.0f) ? m : ((d < 0.0f) ? -m : 0.0f);
        }
        {
            float d = ndf - nd.z;
            float m = 0.005f * __expf(-fabsf(d) * 0.05f);
            o.z += (d > 0.0f) ? m : ((d < 0.0f) ? -m : 0.0f);
        }
        {
            float d = ndf - nd.w;
            float m = 0.005f * __expf(-fabsf(d) * 0.05f);
            o.w += (d > 0.0f) ? m : ((d < 0.0f) ? -m : 0.0f);
        }
        __stcs(&orow[c], o);
    }
}

// ---------------------------------------------------------------------------
// Fused persistent kernel. smem: nd[N] (32KB dynamic) + 1KB mask + red.
// Double-buffered register rows; membrane/dfire prefetched with the row.
// ---------------------------------------------------------------------------
__global__ void __launch_bounds__(BLOCK, 2)
stdp_fused(const float* __restrict__ W,
           const float* __restrict__ spikes,
           const float* __restrict__ dpre,
           const float* __restrict__ membrane,
           const float* __restrict__ dfire,
           float* __restrict__ out) {
    extern __shared__ float s_nd[];              // [N]
    __shared__ uint32_t s_mask[NWORDS];          // spike bitmask
    __shared__ float s_red[2][BLOCK / 32];

    const int tid = threadIdx.x;
    const int lane = tid & 31;
    const int wid = tid >> 5;

    // Issue first W-row loads immediately (overlap with prologue).
    float4 wA[CHUNKS], wB[CHUNKS];
    int row = blockIdx.x;
    load_row(wA, W, row, tid);
    float mS[2], dS[2];
    mS[0] = membrane[row];
    dS[0] = dfire[row];

    // Prologue: new_delta_pre -> smem (+ global, CTA 0 only) and spike mask.
    {
        float4* ndp_out4 = (float4*)(out + 2 * N);
        const float4* sp4 = (const float4*)spikes;
        const float4* dp4 = (const float4*)dpre;
        for (int i = tid; i < N / 4; i += BLOCK) {
            float4 s = sp4[i];
            float4 d = dp4[i];
            float4 nd;
            nd.x = (s.x > 0.0f) ? 0.0f : (d.x + 1.0f);
            nd.y = (s.y > 0.0f) ? 0.0f : (d.y + 1.0f);
            nd.z = (s.z > 0.0f) ? 0.0f : (d.z + 1.0f);
            nd.w = (s.w > 0.0f) ? 0.0f : (d.w + 1.0f);
            ((float4*)s_nd)[i] = nd;
            if (blockIdx.x == 0) ndp_out4[i] = nd;
        }
        // Bitmask: word u covers columns 32u..32u+31; lane l -> column 32u+l.
        for (int u = wid; u < NWORDS; u += BLOCK / 32) {
            float s = spikes[u * 32 + lane];
            uint32_t m = __ballot_sync(0xFFFFFFFFu, s > 0.0f);
            if (lane == 0) s_mask[u] = m;
        }
    }
    __syncthreads();

    int par = 0;
    bool useA = true;
    while (row < N) {
        int nrow = row + GRID;
        if (nrow < N) { mS[par ^ 1] = membrane[nrow]; dS[par ^ 1] = dfire[nrow]; }
        if (useA) {
            if (nrow < N) load_row(wB, W, nrow, tid);      // prefetch next row
            process_row(wA, row, par, s_nd, s_mask, s_red, mS[par], dS[par], out, tid);
        } else {
            if (nrow < N) load_row(wA, W, nrow, tid);
            process_row(wB, row, par, s_nd, s_mask, s_red, mS[par], dS[par], out, tid);
        }
        useA = !useA;
        par ^= 1;
        row = nrow;
    }
}

// ---------------------------------------------------------------------------
// kernel_launch: inputs in metadata order
//   0: in_spikes [8192]  1: weights [8192*8192]  2: membrane [8192]
//   3: delta_pre [8192]  4: delta_fire [8192]
// out layout: [out_spikes | new_membrane | new_delta_pre | new_delta_fire | new_weights]
// ---------------------------------------------------------------------------
extern "C" void kernel_launch(void* const* d_in, const int* in_sizes, int n_in,
                              void* d_out, int out_size) {
    const float* spikes   = (const float*)d_in[0];
    const float* weights  = (const float*)d_in[1];
    const float* membrane = (const float*)d_in[2];
    const float* dpre     = (const float*)d_in[3];
    const float* dfire    = (const float*)d_in[4];
    float* out = (float*)d_out;

    (void)in_sizes; (void)n_in; (void)out_size;

    const int smem_bytes = N * sizeof(float);  // 32 KB
    cudaFuncSetAttribute(stdp_fused,
                         cudaFuncAttributeMaxDynamicSharedMemorySize, smem_bytes);

    stdp_fused<<<GRID, BLOCK, smem_bytes>>>(weights, spikes, dpre,
                                            membrane, dfire, out);
}

// round 7
// speedup vs baseline: 1.0457x; 1.0457x over previous
#include <cuda_runtime.h>
#include <cstdint>

#define N 8192
#define BLOCK 256
#define CHUNKS 8          // per-thread float4 chunks: 8 * 4 * 256 = 8192 cols
#define GRID 296          // 148 SMs * 2 CTAs/SM, persistent

// ---------------------------------------------------------------------------
// Row helpers.
// ---------------------------------------------------------------------------
__device__ __forceinline__ void load_row(float4 (&w)[CHUNKS],
                                         const float* __restrict__ W,
                                         int row, int tid) {
    const float4* wrow = (const float4*)(W + (size_t)row * N);
#pragma unroll
    for (int k = 0; k < CHUNKS; k++)
        w[k] = __ldcs(&wrow[tid + k * BLOCK]);
}

__device__ __forceinline__ void process_row(
        float4 (&w)[CHUNKS], int row, int par, uint32_t mask_reg,
        const float* __restrict__ s_p, const float* __restrict__ s_q,
        float (*s_red)[BLOCK / 32],
        float mrow, float dfrow,           // prefetched membrane[row], dfire[row]
        float* __restrict__ out, int tid) {
    // Dot with 0/1 spikes via per-thread register bitmask: zero LDS here.
    float acc = 0.0f;
#pragma unroll
    for (int k = 0; k < CHUNKS; k++) {
        uint32_t b = mask_reg >> (k * 4);
        acc += (b & 1u) ? w[k].x : 0.0f;
        acc += (b & 2u) ? w[k].y : 0.0f;
        acc += (b & 4u) ? w[k].z : 0.0f;
        acc += (b & 8u) ? w[k].w : 0.0f;
    }
#pragma unroll
    for (int o = 16; o > 0; o >>= 1)
        acc += __shfl_xor_sync(0xFFFFFFFFu, acc, o);
    if ((tid & 31) == 0) s_red[par][tid >> 5] = acc;
    __syncthreads();   // the ONLY barrier per row (s_red parity-buffered)

    float wsum = 0.0f;
#pragma unroll
    for (int i = 0; i < BLOCK / 32; i++) wsum += s_red[par][i];

    // LIF + row scalars, computed redundantly by every thread.
    float mem   = mrow * 0.99f + wsum;
    float spike = (mem > 1.0f) ? 1.0f : 0.0f;
    float nmem  = (spike > 0.0f) ? (mem - 0.8f) : mem;
    float ndf   = (spike > 0.0f) ? 0.0f : (dfrow + 1.0f);
    if (tid == 0) {
        out[row]         = spike;   // out_spikes
        out[N + row]     = nmem;    // new_membrane
        out[3 * N + row] = ndf;     // new_delta_fire
    }
    float E  = expf(ndf * 0.05f);            // comparison key (monotone transfer)
    float ep = 0.005f * expf(-ndf * 0.05f);
    float en = 0.005f * E;

    float4* orow = (float4*)(out + 4 * N + (size_t)row * N);
#pragma unroll
    for (int k = 0; k < CHUNKS; k++) {
        int c = tid + k * BLOCK;
        float4 p = ((const float4*)s_p)[c];
        float4 q = ((const float4*)s_q)[c];
        float4 o = w[k];
        o.x += (E > p.x) ? ep * p.x : ((E < p.x) ? -en * q.x : 0.0f);
        o.y += (E > p.y) ? ep * p.y : ((E < p.y) ? -en * q.y : 0.0f);
        o.z += (E > p.z) ? ep * p.z : ((E < p.z) ? -en * q.z : 0.0f);
        o.w += (E > p.w) ? ep * p.w : ((E < p.w) ? -en * q.w : 0.0f);
        __stcs(&orow[c], o);
    }
}

// ---------------------------------------------------------------------------
// Fused persistent kernel. smem: p[N], q[N] (64 KB) -> 2 CTAs/SM.
// Double-buffered register rows; membrane/dfire prefetched with the row;
// spike mask held in one register per thread.
// ---------------------------------------------------------------------------
__global__ void __launch_bounds__(BLOCK, 2)
stdp_fused(const float* __restrict__ W,
           const float* __restrict__ spikes,
           const float* __restrict__ dpre,
           const float* __restrict__ membrane,
           const float* __restrict__ dfire,
           float* __restrict__ out) {
    extern __shared__ float sm[];
    float* s_p = sm;           // [N]  exp(ndp_j/20)
    float* s_q = sm + N;       // [N]  exp(-ndp_j/20)
    __shared__ float s_red[2][BLOCK / 32];

    const int tid = threadIdx.x;

    // Issue first W-row loads immediately (overlap with prologue).
    float4 wA[CHUNKS], wB[CHUNKS];
    int row = blockIdx.x;
    load_row(wA, W, row, tid);
    float mS[2], dS[2];
    mS[0] = membrane[row];
    dS[0] = dfire[row];

    // Prologue: p/q into smem; spike bits for THIS thread's dot columns into
    // one register (prologue stride tid + t*BLOCK == dot chunk stride).
    uint32_t mask_reg = 0;
    {
        float4* ndp_out4 = (float4*)(out + 2 * N);  // new_delta_pre region
        const float4* sp4 = (const float4*)spikes;
        const float4* dp4 = (const float4*)dpre;
#pragma unroll
        for (int t = 0; t < CHUNKS; t++) {
            int i = tid + t * BLOCK;
            float4 s = sp4[i];
            float4 d = dp4[i];
            float4 nd;
            nd.x = (s.x > 0.0f) ? 0.0f : (d.x + 1.0f);
            nd.y = (s.y > 0.0f) ? 0.0f : (d.y + 1.0f);
            nd.z = (s.z > 0.0f) ? 0.0f : (d.z + 1.0f);
            nd.w = (s.w > 0.0f) ? 0.0f : (d.w + 1.0f);
            if (blockIdx.x == 0) ndp_out4[i] = nd;
            mask_reg |= ((s.x > 0.0f) ? 1u : 0u) << (t * 4);
            mask_reg |= ((s.y > 0.0f) ? 2u : 0u) << (t * 4);
            mask_reg |= ((s.z > 0.0f) ? 4u : 0u) << (t * 4);
            mask_reg |= ((s.w > 0.0f) ? 8u : 0u) << (t * 4);
            float4 p, q;
            p.x = expf(nd.x * 0.05f);  q.x = expf(-nd.x * 0.05f);
            p.y = expf(nd.y * 0.05f);  q.y = expf(-nd.y * 0.05f);
            p.z = expf(nd.z * 0.05f);  q.z = expf(-nd.z * 0.05f);
            p.w = expf(nd.w * 0.05f);  q.w = expf(-nd.w * 0.05f);
            ((float4*)s_p)[i] = p;
            ((float4*)s_q)[i] = q;
        }
    }
    __syncthreads();

    int par = 0;
    bool useA = true;
    while (row < N) {
        int nrow = row + GRID;
        if (nrow < N) { mS[par ^ 1] = membrane[nrow]; dS[par ^ 1] = dfire[nrow]; }
        if (useA) {
            if (nrow < N) load_row(wB, W, nrow, tid);      // prefetch next row
            process_row(wA, row, par, mask_reg, s_p, s_q, s_red,
                        mS[par], dS[par], out, tid);
        } else {
            if (nrow < N) load_row(wA, W, nrow, tid);
            process_row(wB, row, par, mask_reg, s_p, s_q, s_red,
                        mS[par], dS[par], out, tid);
        }
        useA = !useA;
        par ^= 1;
        row = nrow;
    }
}

// ---------------------------------------------------------------------------
// kernel_launch: inputs in metadata order
//   0: in_spikes [8192]  1: weights [8192*8192]  2: membrane [8192]
//   3: delta_pre [8192]  4: delta_fire [8192]
// out layout: [out_spikes | new_membrane | new_delta_pre | new_delta_fire | new_weights]
// ---------------------------------------------------------------------------
extern "C" void kernel_launch(void* const* d_in, const int* in_sizes, int n_in,
                              void* d_out, int out_size) {
    const float* spikes   = (const float*)d_in[0];
    const float* weights  = (const float*)d_in[1];
    const float* membrane = (const float*)d_in[2];
    const float* dpre     = (const float*)d_in[3];
    const float* dfire    = (const float*)d_in[4];
    float* out = (float*)d_out;

    (void)in_sizes; (void)n_in; (void)out_size;

    const int smem_bytes = 2 * N * sizeof(float);  // 64 KB
    cudaFuncSetAttribute(stdp_fused,
                         cudaFuncAttributeMaxDynamicSharedMemorySize, smem_bytes);

    stdp_fused<<<GRID, BLOCK, smem_bytes>>>(weights, spikes, dpre,
                                            membrane, dfire, out);
}